// round 6
// baseline (speedup 1.0000x reference)
#include <cuda_runtime.h>
#include <cstdint>
#include <math.h>

#define HDIM 1024
#define FDIM 2048
#define NEXP 8
#define NTOK 4096
#define NROWS_ROUTED 8192
#define NROWS_TOTAL 12288

// ---------------- scratch (static device globals; no allocation) ----------------
__device__ float g_act[(size_t)NROWS_TOTAL * FDIM];   // silu(gate)*up per row
__device__ float g_y[(size_t)NROWS_TOTAL * HDIM];     // down outputs per row
__device__ int   g_rowtok[NROWS_TOTAL];               // token index per sorted row
__device__ int   g_tokpos[NTOK * 2];                  // expert id (routing) -> row position
__device__ float g_tokw[NTOK * 2];                    // top-2 normalized weights
__device__ float g_imp[NEXP];
__device__ int   g_load[NEXP];
__device__ float g_z2;
__device__ int   g_cnt[NEXP];
__device__ int   g_off[NEXP];
__device__ int   g_cur[NEXP];

// ---------------- packed f32x2 helpers ----------------
typedef unsigned long long u64;

__device__ __forceinline__ u64 pack2(float x, float y) {
    u64 r; asm("mov.b64 %0, {%1, %2};" : "=l"(r) : "f"(x), "f"(y)); return r;
}
__device__ __forceinline__ u64 ffma2(u64 a, u64 b, u64 c) {
    u64 d; asm("fma.rn.f32x2 %0, %1, %2, %3;" : "=l"(d) : "l"(a), "l"(b), "l"(c)); return d;
}
__device__ __forceinline__ float2 unpack2(u64 v) {
    float2 f; asm("mov.b64 {%0, %1}, %2;" : "=f"(f.x), "=f"(f.y) : "l"(v)); return f;
}

// ---------------- init ----------------
__global__ void init_kernel() {
    int t = threadIdx.x;
    if (t < NEXP) { g_imp[t] = 0.f; g_load[t] = 0; g_cnt[t] = 0; }
    if (t == NEXP) g_z2 = 0.f;
}

// ---------------- router: logits, softmax, top-2, aux stats ----------------
__global__ void router_kernel(const float* __restrict__ x, const float* __restrict__ wr) {
    int n = blockIdx.x;
    int tid = threadIdx.x;
    int w = tid >> 5, lane = tid & 31;
    const float* xr = x + (size_t)n * HDIM;
    const float* we = wr + (size_t)w * HDIM;
    float s = 0.f;
    for (int j = lane; j < HDIM; j += 32) s += xr[j] * we[j];
    #pragma unroll
    for (int o = 16; o; o >>= 1) s += __shfl_xor_sync(0xffffffffu, s, o);
    __shared__ float lg[NEXP];
    if (lane == 0) lg[w] = s;
    __syncthreads();
    if (tid == 0) {
        float l[NEXP], p[NEXP];
        float m = -1e30f;
        #pragma unroll
        for (int e = 0; e < NEXP; e++) { l[e] = lg[e]; m = fmaxf(m, l[e]); }
        float se = 0.f;
        #pragma unroll
        for (int e = 0; e < NEXP; e++) { p[e] = expf(l[e] - m); se += p[e]; }
        float inv = 1.f / se;
        #pragma unroll
        for (int e = 0; e < NEXP; e++) { p[e] *= inv; atomicAdd(&g_imp[e], p[e]); }
        float z = m + logf(se);
        atomicAdd(&g_z2, z * z);
        // top-2, first-occurrence tie-break (matches jax.lax.top_k)
        int i1 = 0;
        #pragma unroll
        for (int e = 1; e < NEXP; e++) if (p[e] > p[i1]) i1 = e;
        int i2 = -1;
        #pragma unroll
        for (int e = 0; e < NEXP; e++) {
            if (e == i1) continue;
            if (i2 < 0 || p[e] > p[i2]) i2 = e;
        }
        float denom = p[i1] + p[i2] + 1e-9f;
        g_tokw[n * 2 + 0] = p[i1] / denom;
        g_tokw[n * 2 + 1] = p[i2] / denom;
        atomicAdd(&g_load[i1], 1);
        atomicAdd(&g_cnt[i1], 1);
        atomicAdd(&g_cnt[i2], 1);
        g_tokpos[n * 2 + 0] = i1;
        g_tokpos[n * 2 + 1] = i2;
    }
}

__global__ void prefix_kernel() {
    int o = 0;
    for (int e = 0; e < NEXP; e++) { g_off[e] = o; o += g_cnt[e]; g_cur[e] = 0; }
}

__global__ void scatter_kernel() {
    int n = blockIdx.x * blockDim.x + threadIdx.x;
    if (n < NTOK) {
        #pragma unroll
        for (int k = 0; k < 2; k++) {
            int e = g_tokpos[n * 2 + k];
            int p = g_off[e] + atomicAdd(&g_cur[e], 1);
            g_rowtok[p] = n;
            g_tokpos[n * 2 + k] = p;
        }
        g_rowtok[NROWS_ROUTED + n] = n; // shared-expert group rows
    }
}

// ---------------- grouped GEMMs ----------------
#define BM 128
#define BN 64
#define BK 16

// Fused gate+up: act[r][f] = silu(A[r].Wg[e][f]) * (A[r].Wu[e][f]), K = HDIM
__global__ void __launch_bounds__(256, 2)
gemm_gu_kernel(const float* __restrict__ x,
               const float* __restrict__ weg, const float* __restrict__ wshg,
               const float* __restrict__ weu, const float* __restrict__ wshu) {
    const int g = blockIdx.y;
    int off, cnt;
    if (g < NEXP) { off = g_off[g]; cnt = g_cnt[g]; }
    else          { off = NROWS_ROUTED; cnt = NTOK; }
    const int row0 = blockIdx.x * BM;
    if (row0 >= cnt) return;

    const float* Bg = (g < NEXP) ? (weg + (size_t)g * ((size_t)FDIM * HDIM)) : wshg;
    const float* Bu = (g < NEXP) ? (weu + (size_t)g * ((size_t)FDIM * HDIM)) : wshu;
    const int n0 = blockIdx.z * BN;

    __shared__ float As [BK][BM + 4];
    __shared__ float Bgs[BK][BN + 4];
    __shared__ float Bus[BK][BN + 4];
    __shared__ const float* Arow[BM];

    const int tid = threadIdx.x;
    if (tid < BM) {
        int r = row0 + tid;
        int rc = (r < cnt) ? r : (cnt - 1);
        Arow[tid] = x + (size_t)g_rowtok[off + rc] * HDIM;
    }
    __syncthreads();

    u64 accg[8][2], accu[8][2];
    #pragma unroll
    for (int i = 0; i < 8; i++) { accg[i][0] = accg[i][1] = 0ull; accu[i][0] = accu[i][1] = 0ull; }

    const int tr = tid >> 4, tc = tid & 15;
    const int lm = tid >> 2, lk = tid & 3;      // A-load: row lm, k-quad lk
    const int bn = tid >> 2, bk = tid & 3;      // B-load: col bn, k-quad bk

    const float* aptr0 = Arow[lm]      + lk * 4;
    const float* aptr1 = Arow[lm + 64] + lk * 4;

    for (int kt = 0; kt < HDIM; kt += BK) {
        {
            float4 v = *(const float4*)(aptr0 + kt);
            As[lk * 4 + 0][lm] = v.x; As[lk * 4 + 1][lm] = v.y;
            As[lk * 4 + 2][lm] = v.z; As[lk * 4 + 3][lm] = v.w;
            float4 w = *(const float4*)(aptr1 + kt);
            As[lk * 4 + 0][lm + 64] = w.x; As[lk * 4 + 1][lm + 64] = w.y;
            As[lk * 4 + 2][lm + 64] = w.z; As[lk * 4 + 3][lm + 64] = w.w;
        }
        {
            size_t boff = (size_t)(n0 + bn) * HDIM + kt + bk * 4;
            float4 vg = *(const float4*)(Bg + boff);
            Bgs[bk * 4 + 0][bn] = vg.x; Bgs[bk * 4 + 1][bn] = vg.y;
            Bgs[bk * 4 + 2][bn] = vg.z; Bgs[bk * 4 + 3][bn] = vg.w;
            float4 vu = *(const float4*)(Bu + boff);
            Bus[bk * 4 + 0][bn] = vu.x; Bus[bk * 4 + 1][bn] = vu.y;
            Bus[bk * 4 + 2][bn] = vu.z; Bus[bk * 4 + 3][bn] = vu.w;
        }
        __syncthreads();
        #pragma unroll
        for (int kk = 0; kk < BK; kk++) {
            float4 a0 = *(const float4*)&As[kk][tr * 8];
            float4 a1 = *(const float4*)&As[kk][tr * 8 + 4];
            ulonglong2 bg2 = *(const ulonglong2*)&Bgs[kk][tc * 4];
            ulonglong2 bu2 = *(const ulonglong2*)&Bus[kk][tc * 4];
            u64 a2[8];
            a2[0] = pack2(a0.x, a0.x); a2[1] = pack2(a0.y, a0.y);
            a2[2] = pack2(a0.z, a0.z); a2[3] = pack2(a0.w, a0.w);
            a2[4] = pack2(a1.x, a1.x); a2[5] = pack2(a1.y, a1.y);
            a2[6] = pack2(a1.z, a1.z); a2[7] = pack2(a1.w, a1.w);
            #pragma unroll
            for (int i = 0; i < 8; i++) {
                accg[i][0] = ffma2(a2[i], bg2.x, accg[i][0]);
                accg[i][1] = ffma2(a2[i], bg2.y, accg[i][1]);
                accu[i][0] = ffma2(a2[i], bu2.x, accu[i][0]);
                accu[i][1] = ffma2(a2[i], bu2.y, accu[i][1]);
            }
        }
        __syncthreads();
    }

    #pragma unroll
    for (int i = 0; i < 8; i++) {
        int r = row0 + tr * 8 + i;
        if (r < cnt) {
            float* o = g_act + (size_t)(off + r) * FDIM + n0 + tc * 4;
            #pragma unroll
            for (int jp = 0; jp < 2; jp++) {
                float2 gg = unpack2(accg[i][jp]);
                float2 uu = unpack2(accu[i][jp]);
                o[jp * 2 + 0] = (gg.x / (1.f + __expf(-gg.x))) * uu.x;
                o[jp * 2 + 1] = (gg.y / (1.f + __expf(-gg.y))) * uu.y;
            }
        }
    }
}

// Down: y[r][h] = act[r] . Wd[e][h], K = FDIM
__global__ void __launch_bounds__(256, 2)
gemm_down_kernel(const float* __restrict__ wed, const float* __restrict__ wshd) {
    const int g = blockIdx.y;
    int off, cnt;
    if (g < NEXP) { off = g_off[g]; cnt = g_cnt[g]; }
    else          { off = NROWS_ROUTED; cnt = NTOK; }
    const int row0 = blockIdx.x * BM;
    if (row0 >= cnt) return;

    const float* Bp = (g < NEXP) ? (wed + (size_t)g * ((size_t)HDIM * FDIM)) : wshd;
    const int n0 = blockIdx.z * BN;

    __shared__ float As[BK][BM + 4];
    __shared__ float Bs[BK][BN + 4];

    const int tid = threadIdx.x;
    const int tr = tid >> 4, tc = tid & 15;
    const int lm = tid >> 2, lk = tid & 3;
    const int bn = tid >> 2, bk = tid & 3;

    // rows are contiguous in g_act for this group
    const int rA  = (row0 + lm      < cnt) ? (row0 + lm)      : (cnt - 1);
    const int rA1 = (row0 + lm + 64 < cnt) ? (row0 + lm + 64) : (cnt - 1);
    const float* a_base0 = g_act + (size_t)(off + rA)  * FDIM + lk * 4;
    const float* a_base1 = g_act + (size_t)(off + rA1) * FDIM + lk * 4;

    u64 acc[8][2];
    #pragma unroll
    for (int i = 0; i < 8; i++) { acc[i][0] = 0ull; acc[i][1] = 0ull; }

    for (int kt = 0; kt < FDIM; kt += BK) {
        {
            float4 v0 = *(const float4*)(a_base0 + kt);
            As[lk * 4 + 0][lm] = v0.x; As[lk * 4 + 1][lm] = v0.y;
            As[lk * 4 + 2][lm] = v0.z; As[lk * 4 + 3][lm] = v0.w;
            float4 v1 = *(const float4*)(a_base1 + kt);
            As[lk * 4 + 0][lm + 64] = v1.x; As[lk * 4 + 1][lm + 64] = v1.y;
            As[lk * 4 + 2][lm + 64] = v1.z; As[lk * 4 + 3][lm + 64] = v1.w;
        }
        {
            float4 v = *(const float4*)(Bp + (size_t)(n0 + bn) * FDIM + kt + bk * 4);
            Bs[bk * 4 + 0][bn] = v.x; Bs[bk * 4 + 1][bn] = v.y;
            Bs[bk * 4 + 2][bn] = v.z; Bs[bk * 4 + 3][bn] = v.w;
        }
        __syncthreads();
        #pragma unroll
        for (int kk = 0; kk < BK; kk++) {
            float4 a0 = *(const float4*)&As[kk][tr * 8];
            float4 a1 = *(const float4*)&As[kk][tr * 8 + 4];
            ulonglong2 b2 = *(const ulonglong2*)&Bs[kk][tc * 4];
            u64 a2[8];
            a2[0] = pack2(a0.x, a0.x); a2[1] = pack2(a0.y, a0.y);
            a2[2] = pack2(a0.z, a0.z); a2[3] = pack2(a0.w, a0.w);
            a2[4] = pack2(a1.x, a1.x); a2[5] = pack2(a1.y, a1.y);
            a2[6] = pack2(a1.z, a1.z); a2[7] = pack2(a1.w, a1.w);
            #pragma unroll
            for (int i = 0; i < 8; i++) {
                acc[i][0] = ffma2(a2[i], b2.x, acc[i][0]);
                acc[i][1] = ffma2(a2[i], b2.y, acc[i][1]);
            }
        }
        __syncthreads();
    }

    #pragma unroll
    for (int i = 0; i < 8; i++) {
        int r = row0 + tr * 8 + i;
        if (r < cnt) {
            float* o = g_y + (size_t)(off + r) * HDIM + n0 + tc * 4;
            float2 v0 = unpack2(acc[i][0]);
            float2 v1 = unpack2(acc[i][1]);
            o[0] = v0.x; o[1] = v0.y; o[2] = v1.x; o[3] = v1.y;
        }
    }
}

// ---------------- combine: y = shared + w0*e0 + w1*e1 ----------------
__global__ void combine_kernel(float* __restrict__ out) {
    int n = blockIdx.x;
    int p0 = g_tokpos[n * 2], p1 = g_tokpos[n * 2 + 1];
    float w0 = g_tokw[n * 2], w1 = g_tokw[n * 2 + 1];
    const float4* ysh = (const float4*)(g_y + (size_t)(NROWS_ROUTED + n) * HDIM);
    const float4* y0  = (const float4*)(g_y + (size_t)p0 * HDIM);
    const float4* y1  = (const float4*)(g_y + (size_t)p1 * HDIM);
    float4* o = (float4*)(out + (size_t)n * HDIM);
    for (int h = threadIdx.x; h < HDIM / 4; h += blockDim.x) {
        float4 s = ysh[h], a = y0[h], b = y1[h], r;
        r.x = s.x + w0 * a.x + w1 * b.x;
        r.y = s.y + w0 * a.y + w1 * b.y;
        r.z = s.z + w0 * a.z + w1 * b.z;
        r.w = s.w + w0 * a.w + w1 * b.w;
        o[h] = r;
    }
}

// ---------------- aux losses ----------------
__global__ void aux_kernel(float* __restrict__ out, int out_size) {
    const int yelems = NTOK * HDIM;
    if (out_size <= yelems) return;
    float imp[NEXP], ld[NEXP];
    float impSum = 0.f, loadSum = 0.f;
    for (int e = 0; e < NEXP; e++) {
        imp[e] = g_imp[e]; ld[e] = (float)g_load[e];
        impSum += imp[e]; loadSum += ld[e];
    }
    float lb = 0.f;
    for (int e = 0; e < NEXP; e++)
        lb += (imp[e] / (impSum + 1e-9f)) * (ld[e] / (loadSum + 1e-9f));
    lb *= (float)NEXP;
    float z_loss = 0.001f * (g_z2 / (float)NTOK);
    out[yelems] = 0.01f * lb + z_loss;
    for (int i = yelems + 1; i < out_size; i++) out[i] = 0.f; // defensive
}

// ---------------- launch ----------------
extern "C" void kernel_launch(void* const* d_in, const int* in_sizes, int n_in,
                              void* d_out, int out_size) {
    const float* x    = (const float*)d_in[0];
    const float* wr   = (const float*)d_in[1];
    const float* wshg = (const float*)d_in[2];
    const float* wshu = (const float*)d_in[3];
    const float* wshd = (const float*)d_in[4];
    const float* weg  = (const float*)d_in[5];
    const float* weu  = (const float*)d_in[6];
    const float* wed  = (const float*)d_in[7];
    float* out = (float*)d_out;

    init_kernel<<<1, 32>>>();
    router_kernel<<<NTOK, 256>>>(x, wr);
    prefix_kernel<<<1, 1>>>();
    scatter_kernel<<<16, 256>>>();

    dim3 gGU(NROWS_ROUTED / BM, NEXP + 1, FDIM / BN);  // (64, 9, 32)
    gemm_gu_kernel<<<gGU, 256>>>(x, weg, wshg, weu, wshu);
    dim3 gD(NROWS_ROUTED / BM, NEXP + 1, HDIM / BN);   // (64, 9, 16)
    gemm_down_kernel<<<gD, 256>>>(wed, wshd);

    combine_kernel<<<NTOK, 256>>>(out);
    aux_kernel<<<1, 1>>>(out, out_size);
}